// round 1
// baseline (speedup 1.0000x reference)
#include <cuda_runtime.h>
#include <math.h>

// ---------------- problem constants (fixed shapes) ----------------
#define NN   40000      // nodes
#define EE   128000     // edges
#define E2C  16000
#define EPGC 32000
#define BC   4
#define ML   128
#define ZETA 1e-6f
#define PEXP 1.852f
#define INVP (1.0f/1.852f)
#define I_LAYERS 3
#define K_ITERS  4
#define J_HEADS  6

#define SELU_SCALE 1.0507009873554805f
#define SELU_ALPHA 1.6732632423543772f
#define ENC_NEGINF 0x007FFFFFu

// ---------------- device scratch (no allocation allowed) ----------------
__device__ float g_buf[NN*ML];
__device__ float agg_buf[NN*ML];      // also aliased as unsigned for atomic max
__device__ float tN_buf[NN*ML];
__device__ float z_buf[(long)EE*ML];
__device__ float tE_buf[(long)EE*ML];
__device__ float qh_buf[EE];
__device__ float qt_buf[EE];
__device__ float hl_buf[EE];
__device__ float dh_buf[NN];
__device__ float hA_buf[NN];
__device__ float hB_buf[NN];
__device__ unsigned aggS_buf[NN];

// ---------------- helpers ----------------
__device__ __forceinline__ float selu_f(float x){
    return x > 0.f ? SELU_SCALE * x : SELU_SCALE * SELU_ALPHA * (__expf(x) - 1.f);
}
__device__ __forceinline__ unsigned fenc(float f){
    unsigned u = __float_as_uint(f);
    return (u >> 31) ? ~u : (u | 0x80000000u);
}
__device__ __forceinline__ float fdec(unsigned u){
    return (u >> 31) ? __uint_as_float(u & 0x7fffffffu) : __uint_as_float(~u);
}
__device__ __forceinline__ float signf(float x){
    return (x > 0.f) ? 1.f : ((x < 0.f) ? -1.f : 0.f);
}

// ---------------- GEMM: C[M x 128] = act( A[M x K] @ B[K x 128] ) ----------------
// MODE 0: A row = selu(concat(A0[iS[row]], A1[iR[row]], A2[row]))   (K = 384)
// MODE 1: A row = selu(concat(A0[row], A1[row]))                    (K = 256)
// MODE 2: A row = A0[row]  (no selu)                                (K = 128)
// In-place (C == A0) is safe for MODE 2: tile rows are read (via smem) before
// any write, and blocks own disjoint row ranges.
template<int KDIM, int MODE, bool ACT>
__global__ void __launch_bounds__(256) gemm128(
    const float* __restrict__ A0, const float* __restrict__ A1,
    const float* __restrict__ A2,
    const int* __restrict__ iS, const int* __restrict__ iR,
    const float* __restrict__ B, float* __restrict__ C, int M)
{
    __shared__ float As[32][65];    // [k][row], pad 65 -> conflict-free
    __shared__ float Bs[32][128];

    const int tid  = threadIdx.x;
    const int row0 = blockIdx.x * 64;
    const int tidx = tid & 31;      // -> 4 cols at tidx*4
    const int tidy = tid >> 5;      // -> 8 rows at tidy*8

    // A-tile load assignment: 64 rows x 32 cols, 8 floats per thread
    const int lrow = tid >> 2;
    const int lc   = (tid & 3) * 8;
    int grow = row0 + lrow;
    if (grow >= M) grow = M - 1;

    const float* rp0 = A0;
    const float* rp1 = A1;
    const float* rp2 = A2;
    if (MODE == 0){
        rp0 = A0 + (long)iS[grow] * ML;
        rp1 = A1 + (long)iR[grow] * ML;
        rp2 = A2 + (long)grow * ML;
    } else {
        rp0 = A0 + (long)grow * ML;
        if (MODE == 1) rp1 = A1 + (long)grow * ML;
    }

    // B-tile load assignment: 32 rows x 128 cols, 16 floats per thread
    const int brow = tid >> 3;
    const int bcol = (tid & 7) * 16;

    float acc[8][4];
    #pragma unroll
    for (int r = 0; r < 8; r++)
        #pragma unroll
        for (int c = 0; c < 4; c++) acc[r][c] = 0.f;

    #pragma unroll 1
    for (int k0 = 0; k0 < KDIM; k0 += 32){
        // ---- A tile (gather + selu fused) ----
        const float* src;
        if (MODE == 0)      src = (k0 < 128) ? (rp0 + k0) : ((k0 < 256) ? (rp1 + (k0-128)) : (rp2 + (k0-256)));
        else if (MODE == 1) src = (k0 < 128) ? (rp0 + k0) : (rp1 + (k0-128));
        else                src = rp0 + k0;

        float4 v0 = *(const float4*)(src + lc);
        float4 v1 = *(const float4*)(src + lc + 4);
        if (MODE != 2){
            v0.x = selu_f(v0.x); v0.y = selu_f(v0.y); v0.z = selu_f(v0.z); v0.w = selu_f(v0.w);
            v1.x = selu_f(v1.x); v1.y = selu_f(v1.y); v1.z = selu_f(v1.z); v1.w = selu_f(v1.w);
        }
        As[lc+0][lrow] = v0.x; As[lc+1][lrow] = v0.y;
        As[lc+2][lrow] = v0.z; As[lc+3][lrow] = v0.w;
        As[lc+4][lrow] = v1.x; As[lc+5][lrow] = v1.y;
        As[lc+6][lrow] = v1.z; As[lc+7][lrow] = v1.w;

        // ---- B tile ----
        const float* bsrc = B + (long)(k0 + brow) * ML + bcol;
        float4 b0 = *(const float4*)(bsrc + 0);
        float4 b1 = *(const float4*)(bsrc + 4);
        float4 b2 = *(const float4*)(bsrc + 8);
        float4 b3 = *(const float4*)(bsrc + 12);
        *(float4*)&Bs[brow][bcol + 0]  = b0;
        *(float4*)&Bs[brow][bcol + 4]  = b1;
        *(float4*)&Bs[brow][bcol + 8]  = b2;
        *(float4*)&Bs[brow][bcol + 12] = b3;

        __syncthreads();

        #pragma unroll
        for (int kk = 0; kk < 32; kk++){
            float a[8];
            #pragma unroll
            for (int r = 0; r < 8; r++) a[r] = As[kk][tidy*8 + r];
            float4 bv = *(const float4*)&Bs[kk][tidx*4];
            #pragma unroll
            for (int r = 0; r < 8; r++){
                acc[r][0] += a[r] * bv.x;
                acc[r][1] += a[r] * bv.y;
                acc[r][2] += a[r] * bv.z;
                acc[r][3] += a[r] * bv.w;
            }
        }
        __syncthreads();
    }

    #pragma unroll
    for (int r = 0; r < 8; r++){
        int row = row0 + tidy*8 + r;
        if (row < M){
            float4 o;
            o.x = ACT ? selu_f(acc[r][0]) : acc[r][0];
            o.y = ACT ? selu_f(acc[r][1]) : acc[r][1];
            o.z = ACT ? selu_f(acc[r][2]) : acc[r][2];
            o.w = ACT ? selu_f(acc[r][3]) : acc[r][3];
            *(float4*)(C + (long)row*ML + tidx*4) = o;
        }
    }
}

// ---------------- elementwise / segment kernels ----------------
__global__ void k_hstar(const float* __restrict__ x, float* __restrict__ h){
    int n = blockIdx.x*blockDim.x + threadIdx.x;
    if (n < NN) h[n] = x[2*n];
}
__global__ void k_copy(const float* __restrict__ a, float* __restrict__ b, int n){
    int i = blockIdx.x*blockDim.x + threadIdx.x;
    if (i < n) b[i] = a[i];
}
__global__ void k_zero(float* __restrict__ p, int n){
    int i = blockIdx.x*blockDim.x + threadIdx.x;
    if (i < n) p[i] = 0.f;
}
__global__ void k_fill_u(unsigned* __restrict__ p, unsigned v, int n){
    int i = blockIdx.x*blockDim.x + threadIdx.x;
    if (i < n) p[i] = v;
}
// q = sign(dh) * ((|dh|+Z)/(r+Z))^(1/P)
__global__ void k_flows(const float* __restrict__ h, const float* __restrict__ r,
                        const int* __restrict__ s, const int* __restrict__ rc,
                        float* __restrict__ q){
    int e = blockIdx.x*blockDim.x + threadIdx.x;
    if (e >= EE) return;
    float dh = h[s[e]] - h[rc[e]];
    q[e] = signf(dh) * __powf((fabsf(dh) + ZETA) / (r[e] + ZETA), INVP);
}
__global__ void k_segsum(const float* __restrict__ q, const int* __restrict__ rc,
                         float* __restrict__ d){
    int e = blockIdx.x*blockDim.x + threadIdx.x;
    if (e < EE) atomicAdd(&d[rc[e]], q[e]);
}
// g = selu([d_hat, d_star]) @ W_node_in
__global__ void k_node_in(const float* __restrict__ dh, const float* __restrict__ x,
                          const float* __restrict__ W, float* __restrict__ g){
    int idx = blockIdx.x*blockDim.x + threadIdx.x;
    if (idx >= NN*ML) return;
    int n = idx >> 7, j = idx & 127;
    g[idx] = selu_f(dh[n]) * W[j] + selu_f(x[2*n+1]) * W[ML + j];
}
// z = selu([q_tilde, q_hat]) @ W_edge_in
__global__ void k_edge_in(const float* __restrict__ qt, const float* __restrict__ qh,
                          const float* __restrict__ W, float* __restrict__ z){
    long idx = (long)blockIdx.x*blockDim.x + threadIdx.x;
    if (idx >= (long)EE*ML) return;
    int e = (int)(idx >> 7), j = (int)(idx & 127);
    z[idx] = selu_f(qt[e]) * W[j] + selu_f(qh[e]) * W[ML + j];
}
__global__ void k_aggmax_vec(const float* __restrict__ z, const int* __restrict__ rc,
                             unsigned* __restrict__ agg){
    long idx = (long)blockIdx.x*blockDim.x + threadIdx.x;
    if (idx >= (long)EE*ML) return;
    int e = (int)(idx >> 7), j = (int)(idx & 127);
    atomicMax(&agg[(long)rc[e]*ML + j], fenc(z[idx]));
}
__global__ void k_agg_decode(unsigned* __restrict__ u, float* __restrict__ out, int n){
    int i = blockIdx.x*blockDim.x + threadIdx.x;
    if (i >= n) return;
    unsigned v = u[i];
    out[i] = (v == ENC_NEGINF) ? 0.f : fdec(v);
}
// q_hat[e] += dot(t2[e,:], Wf3) ; one warp per edge
__global__ void k_qdot(const float* __restrict__ t2, const float* __restrict__ Wf3,
                       float* __restrict__ qh){
    int e = blockIdx.x * 4 + (threadIdx.x >> 5);
    if (e >= EE) return;
    int lane = threadIdx.x & 31;
    const float* row = t2 + (long)e*ML;
    float s = 0.f;
    #pragma unroll
    for (int j = 0; j < 4; j++) s += row[lane + 32*j] * Wf3[lane + 32*j];
    #pragma unroll
    for (int o = 16; o > 0; o >>= 1) s += __shfl_down_sync(0xffffffffu, s, o);
    if (lane == 0) qh[e] += s;
}
__global__ void k_antisym(float* __restrict__ q){
    int idx = blockIdx.x*blockDim.x + threadIdx.x;
    if (idx >= BC*E2C) return;
    int b = idx / E2C, i = idx % E2C;
    q[b*EPGC + E2C + i] = -q[b*EPGC + i];
}
// hl = r * sign(q) * |q|^P
__global__ void k_hl(const float* __restrict__ q, const float* __restrict__ r,
                     float* __restrict__ hl){
    int e = blockIdx.x*blockDim.x + threadIdx.x;
    if (e >= EE) return;
    float qe = q[e];
    float aq = fabsf(qe);
    float p  = (aq < 1e-30f) ? 0.f : __powf(aq, PEXP);
    hl[e] = r[e] * signf(qe) * p;
}
__global__ void k_head_edge(const float* __restrict__ h, const float* __restrict__ hl,
                            const int* __restrict__ s, const int* __restrict__ rc,
                            unsigned* __restrict__ agg){
    int e = blockIdx.x*blockDim.x + threadIdx.x;
    if (e < EE) atomicMax(&agg[rc[e]], fenc(h[s[e]] - hl[e]));
}
__global__ void k_head_node(const unsigned* __restrict__ agg, const float* __restrict__ hold,
                            const float* __restrict__ x, float* __restrict__ hnew){
    int n = blockIdx.x*blockDim.x + threadIdx.x;
    if (n >= NN) return;
    float hs = x[2*n];
    unsigned u = agg[n];
    float a = (u == ENC_NEGINF) ? -INFINITY : fdec(u);
    hnew[n] = (hs != 0.f) ? hs : fmaxf(hold[n], a);
}

// ---------------- host orchestration ----------------
template<typename T>
static T* sym_addr(const void* sym){
    void* p = nullptr;
    cudaGetSymbolAddress(&p, sym);
    return (T*)p;
}

extern "C" void kernel_launch(void* const* d_in, const int* in_sizes, int n_in,
                              void* d_out, int out_size)
{
    const float* x    = (const float*)d_in[0];
    const float* r    = (const float*)d_in[1];
    const float* Wni  = (const float*)d_in[2];
    const float* Wei  = (const float*)d_in[3];
    const float* Wf1  = (const float*)d_in[4];
    const float* Wf2  = (const float*)d_in[5];
    const float* Wf3  = (const float*)d_in[6];
    const float* We1  = (const float*)d_in[7];
    const float* We2  = (const float*)d_in[8];
    const float* Wn1  = (const float*)d_in[9];
    const float* Wn2  = (const float*)d_in[10];
    const int*   sndr = (const int*)d_in[11];
    const int*   rcvr = (const int*)d_in[12];
    float*       out  = (float*)d_out;

    float*    g   = sym_addr<float>(g_buf);
    float*    agg = sym_addr<float>(agg_buf);
    unsigned* agu = (unsigned*)agg;
    float*    tN  = sym_addr<float>(tN_buf);
    float*    z   = sym_addr<float>(z_buf);
    float*    tE  = sym_addr<float>(tE_buf);
    float*    qh  = sym_addr<float>(qh_buf);
    float*    qt  = sym_addr<float>(qt_buf);
    float*    hl  = sym_addr<float>(hl_buf);
    float*    dh  = sym_addr<float>(dh_buf);
    float*    hA  = sym_addr<float>(hA_buf);
    float*    hB  = sym_addr<float>(hB_buf);
    unsigned* agS = sym_addr<unsigned>(aggS_buf);

    const int T = 256;
    const int gN   = (NN + T - 1) / T;
    const int gE   = (EE + T - 1) / T;
    const int gNM  = (NN*ML + T - 1) / T;
    const long EM  = (long)EE*ML;
    const int gEM  = (int)((EM + T - 1) / T);

    // ---- initial flows ----
    k_hstar<<<gN, T>>>(x, hA);
    k_flows<<<gE, T>>>(hA, r, sndr, rcvr, qh);
    k_zero<<<gN, T>>>(dh, NN);
    k_segsum<<<gE, T>>>(qh, rcvr, dh);
    k_copy<<<gE, T>>>(qh, qt, EE);

    for (int k = 0; k < K_ITERS; k++){
        k_node_in<<<gNM, T>>>(dh, x, Wni, g);
        k_edge_in<<<gEM, T>>>(qt, qh, Wei, z);

        for (int i = 0; i < I_LAYERS; i++){
            // z' = selu(selu([g_s, g_r, z]) @ We1) @ We2
            gemm128<384,0,true ><<<EE/64, 256>>>(g, g, z, sndr, rcvr,
                                                 We1 + (long)i*384*ML, tE, EE);
            gemm128<128,2,false><<<EE/64, 256>>>(tE, nullptr, nullptr, nullptr, nullptr,
                                                 We2 + (long)i*ML*ML, z, EE);
            // agg = segment_max(z, rcvr), empty -> 0
            k_fill_u<<<gNM, T>>>(agu, ENC_NEGINF, NN*ML);
            k_aggmax_vec<<<gEM, T>>>(z, rcvr, agu);
            k_agg_decode<<<gNM, T>>>(agu, agg, NN*ML);
            // g = selu(selu([g, agg]) @ Wn1) @ Wn2
            gemm128<256,1,true ><<<NN/64, 256>>>(g, agg, nullptr, nullptr, nullptr,
                                                 Wn1 + (long)i*256*ML, tN, NN);
            gemm128<128,2,false><<<NN/64, 256>>>(tN, nullptr, nullptr, nullptr, nullptr,
                                                 Wn2 + (long)i*ML*ML, g, NN);
        }

        // q_hat += selu(selu(selu([g_s,g_r,z]) @ Wf1) @ Wf2) @ Wf3
        gemm128<384,0,true><<<EE/64, 256>>>(g, g, z, sndr, rcvr, Wf1, tE, EE);
        gemm128<128,2,true><<<EE/64, 256>>>(tE, nullptr, nullptr, nullptr, nullptr,
                                            Wf2, tE, EE);   // in-place, safe
        k_qdot<<<EE/4, 128>>>(tE, Wf3, qh);
        k_antisym<<<(BC*E2C + T - 1)/T, T>>>(qh);

        // d_hat = segment_sum(q_hat)
        k_zero<<<gN, T>>>(dh, NN);
        k_segsum<<<gE, T>>>(qh, rcvr, dh);

        // h_tilde = construct_heads(h_star, q_hat)
        k_hstar<<<gN, T>>>(x, hA);
        k_hl<<<gE, T>>>(qh, r, hl);
        float* hc = hA; float* hn = hB;
        for (int j = 0; j < J_HEADS; j++){
            k_fill_u<<<gN, T>>>(agS, ENC_NEGINF, NN);
            k_head_edge<<<gE, T>>>(hc, hl, sndr, rcvr, agS);
            k_head_node<<<gN, T>>>(agS, hc, x, hn);
            float* t2 = hc; hc = hn; hn = t2;
        }
        // J_HEADS = 6 (even) -> result is in hA (== hc)

        // q_tilde = net flows(h_tilde)
        k_flows<<<gE, T>>>(hc, r, sndr, rcvr, qt);
    }

    k_copy<<<gN, T>>>(hA, out, NN);
    (void)in_sizes; (void)n_in; (void)out_size;
}

// round 2
// speedup vs baseline: 1.1992x; 1.1992x over previous
#include <cuda_runtime.h>
#include <math.h>

// ---------------- problem constants ----------------
#define NN   40000
#define EE   128000
#define E2C  16000
#define EPGC 32000
#define BC   4
#define ML   128
#define ZETA 1e-6f
#define PEXP 1.852f
#define INVP (1.0f/1.852f)
#define I_LAYERS 3
#define K_ITERS  4
#define J_HEADS  6

#define SELU_SCALE 1.0507009873554805f
#define SELU_ALPHA 1.6732632423543772f
#define ENC_NEGINF 0x007FFFFFu

// ---------------- device scratch ----------------
__device__ float    g_buf[NN*ML];
__device__ unsigned agg_buf[NN*ML];
__device__ float    tN_buf[NN*ML];
__device__ float    u_buf[NN*ML];
__device__ float    v_buf[NN*ML];
__device__ float    z_buf[(size_t)EE*ML];
__device__ float    w_buf[(size_t)EE*ML];
__device__ float    qh_buf[EE];
__device__ float    qt_buf[EE];
__device__ float    hl_buf[EE];
__device__ float    dh_buf[NN];
__device__ float    hA_buf[NN];
__device__ float    hB_buf[NN];
__device__ unsigned aggS_buf[NN];

// ---------------- helpers ----------------
__device__ __forceinline__ float selu_f(float x){
    return x > 0.f ? SELU_SCALE * x : SELU_SCALE * SELU_ALPHA * (__expf(x) - 1.f);
}
__device__ __forceinline__ unsigned fenc(float f){
    unsigned u = __float_as_uint(f);
    return (u >> 31) ? ~u : (u | 0x80000000u);
}
__device__ __forceinline__ float fdec(unsigned u){
    return (u >> 31) ? __uint_as_float(u & 0x7fffffffu) : __uint_as_float(~u);
}
__device__ __forceinline__ float signf(float x){
    return (x > 0.f) ? 1.f : ((x < 0.f) ? -1.f : 0.f);
}
// packed f32x2 FMA (FFMA2) — only reachable via PTX on sm_103a
__device__ __forceinline__ void fma2(unsigned long long& d,
                                     unsigned long long a, unsigned long long b){
    asm("fma.rn.f32x2 %0, %1, %2, %0;" : "+l"(d) : "l"(a), "l"(b));
}
__device__ __forceinline__ float f2lo(unsigned long long v){ return __uint_as_float((unsigned)v); }
__device__ __forceinline__ float f2hi(unsigned long long v){ return __uint_as_float((unsigned)(v>>32)); }

// ---------------- GEMM2: C[M x 128] = act(A'[M x KDIM] @ B[KDIM x 128]) ----------------
// A-row construction (MODE):
//   M_PLAIN : A0[row]                              (K=128)
//   M_SELU  : selu(A0[row])                        (K=128)
//   M_SUM3  : selu(A0[iS[row]]+A1[iR[row]]+A2[row])(K=128)
//   M_CAT2D : [selu(A0[row]), selu(dec(AU[row]))]  (K=256)
// Epilogue flags: OUTACT (selu), AGGMAX (atomicMax into aggU by rcv[row]),
//                 DOTOUT (qout[row] += dot(actRow, Wf3); no C write).
// gridDim.y==2 selects B row-block y*128 and C vs C2 (u/v pair).
enum { M_PLAIN=0, M_SELU=1, M_SUM3=2, M_CAT2D=3 };
#define KB 16
#define ASTR 260   // dup'd A stride (floats): mult of 4 -> 16B-aligned rows

template<int KDIM, int MODE, bool OUTACT, bool AGGMAX, bool DOTOUT>
__global__ void __launch_bounds__(256,2) gemm2(
    const float* __restrict__ A0, const float* __restrict__ A1,
    const float* __restrict__ A2, const unsigned* __restrict__ AU,
    const int* __restrict__ iS, const int* __restrict__ iR,
    const float* __restrict__ B, float* __restrict__ C, float* __restrict__ C2,
    unsigned* __restrict__ aggU, const int* __restrict__ rcv,
    const float* __restrict__ Wf3, float* __restrict__ qout, int M)
{
    __shared__ float Asd[KB][ASTR];   // each a stored twice: Asd[k][2r]==Asd[k][2r+1]
    __shared__ float Bs[KB][128];

    const int tid  = threadIdx.x;
    const int row0 = blockIdx.x * 128;
    if (blockIdx.y){ B += (size_t)128*128; C = C2; }

    const int lane  = tid & 31;
    const int lane4 = lane * 4;
    const int wrow  = (tid >> 5) * 16;

    // ---- A staging assignment: 128 rows x 16 k, 8 floats/thread ----
    const int arow = tid >> 1;
    const int ak   = (tid & 1) * 8;
    int grow = row0 + arow; if (grow > M-1) grow = M-1;

    const float*    pA0 = nullptr;
    const float*    pA1 = nullptr;
    const float*    pA2 = nullptr;
    const unsigned* pAU = nullptr;
    if (MODE == M_SUM3){
        pA0 = A0 + (size_t)iS[grow]*ML;
        pA1 = A1 + (size_t)iR[grow]*ML;
        pA2 = A2 + (size_t)grow*ML;
    } else {
        pA0 = A0 + (size_t)grow*ML;
        if (MODE == M_CAT2D) pAU = AU + (size_t)grow*ML;
    }

    // ---- B staging assignment: 16 k x 128 cols, 8 floats/thread ----
    const int brow = tid >> 4;
    const int bcol = (tid & 15) * 8;

    unsigned long long acc[16][2];
    #pragma unroll
    for (int r = 0; r < 16; r++){ acc[r][0] = 0ull; acc[r][1] = 0ull; }

    #pragma unroll 1
    for (int k0 = 0; k0 < KDIM; k0 += KB){
        // ---- A tile ----
        float vals[8];
        if (MODE == M_SUM3){
            float4 x0 = *(const float4*)(pA0 + k0 + ak);
            float4 x1 = *(const float4*)(pA0 + k0 + ak + 4);
            float4 y0 = *(const float4*)(pA1 + k0 + ak);
            float4 y1 = *(const float4*)(pA1 + k0 + ak + 4);
            float4 z0 = *(const float4*)(pA2 + k0 + ak);
            float4 z1 = *(const float4*)(pA2 + k0 + ak + 4);
            vals[0]=selu_f(x0.x+y0.x+z0.x); vals[1]=selu_f(x0.y+y0.y+z0.y);
            vals[2]=selu_f(x0.z+y0.z+z0.z); vals[3]=selu_f(x0.w+y0.w+z0.w);
            vals[4]=selu_f(x1.x+y1.x+z1.x); vals[5]=selu_f(x1.y+y1.y+z1.y);
            vals[6]=selu_f(x1.z+y1.z+z1.z); vals[7]=selu_f(x1.w+y1.w+z1.w);
        } else if (MODE == M_SELU){
            float4 x0 = *(const float4*)(pA0 + k0 + ak);
            float4 x1 = *(const float4*)(pA0 + k0 + ak + 4);
            vals[0]=selu_f(x0.x); vals[1]=selu_f(x0.y); vals[2]=selu_f(x0.z); vals[3]=selu_f(x0.w);
            vals[4]=selu_f(x1.x); vals[5]=selu_f(x1.y); vals[6]=selu_f(x1.z); vals[7]=selu_f(x1.w);
        } else if (MODE == M_PLAIN){
            float4 x0 = *(const float4*)(pA0 + k0 + ak);
            float4 x1 = *(const float4*)(pA0 + k0 + ak + 4);
            vals[0]=x0.x; vals[1]=x0.y; vals[2]=x0.z; vals[3]=x0.w;
            vals[4]=x1.x; vals[5]=x1.y; vals[6]=x1.z; vals[7]=x1.w;
        } else { // M_CAT2D
            if (k0 < ML){
                float4 x0 = *(const float4*)(pA0 + k0 + ak);
                float4 x1 = *(const float4*)(pA0 + k0 + ak + 4);
                vals[0]=selu_f(x0.x); vals[1]=selu_f(x0.y); vals[2]=selu_f(x0.z); vals[3]=selu_f(x0.w);
                vals[4]=selu_f(x1.x); vals[5]=selu_f(x1.y); vals[6]=selu_f(x1.z); vals[7]=selu_f(x1.w);
            } else {
                uint4 u0 = *(const uint4*)(pAU + (k0-ML) + ak);
                uint4 u1 = *(const uint4*)(pAU + (k0-ML) + ak + 4);
                unsigned uu[8] = {u0.x,u0.y,u0.z,u0.w,u1.x,u1.y,u1.z,u1.w};
                #pragma unroll
                for (int j = 0; j < 8; j++){
                    float d = (uu[j] == ENC_NEGINF) ? 0.f : fdec(uu[j]);
                    vals[j] = selu_f(d);
                }
            }
        }
        #pragma unroll
        for (int j = 0; j < 8; j++)
            *(float2*)&Asd[ak+j][2*arow] = make_float2(vals[j], vals[j]);

        // ---- B tile ----
        {
            const float* bp = B + (size_t)(k0 + brow)*ML + bcol;
            *(float4*)&Bs[brow][bcol]     = *(const float4*)(bp);
            *(float4*)&Bs[brow][bcol + 4] = *(const float4*)(bp + 4);
        }
        __syncthreads();

        // ---- compute: 16 rows x 4 cols per thread, packed f32x2 ----
        #pragma unroll 4
        for (int kk = 0; kk < KB; kk++){
            ulonglong2 b = *(const ulonglong2*)&Bs[kk][lane4];
            #pragma unroll
            for (int p = 0; p < 8; p++){
                ulonglong2 a = *(const ulonglong2*)&Asd[kk][(wrow + 2*p)*2];
                fma2(acc[2*p  ][0], a.x, b.x);
                fma2(acc[2*p  ][1], a.x, b.y);
                fma2(acc[2*p+1][0], a.y, b.x);
                fma2(acc[2*p+1][1], a.y, b.y);
            }
        }
        __syncthreads();
    }

    // ---- epilogue ----
    float w3x=0.f, w3y=0.f, w3z=0.f, w3w=0.f;
    if (DOTOUT){
        float4 wv = *(const float4*)(Wf3 + lane4);
        w3x=wv.x; w3y=wv.y; w3z=wv.z; w3w=wv.w;
    }
    #pragma unroll
    for (int r = 0; r < 16; r++){
        float v0 = f2lo(acc[r][0]), v1 = f2hi(acc[r][0]);
        float v2 = f2lo(acc[r][1]), v3 = f2hi(acc[r][1]);
        if (OUTACT){ v0=selu_f(v0); v1=selu_f(v1); v2=selu_f(v2); v3=selu_f(v3); }
        int row = row0 + wrow + r;
        if (DOTOUT){
            float s = v0*w3x + v1*w3y + v2*w3z + v3*w3w;
            #pragma unroll
            for (int o = 16; o > 0; o >>= 1) s += __shfl_down_sync(0xffffffffu, s, o);
            if (lane == 0 && row < M) qout[row] += s;
        } else if (row < M){
            *(float4*)(C + (size_t)row*ML + lane4) = make_float4(v0,v1,v2,v3);
            if (AGGMAX){
                unsigned* ab = aggU + (size_t)rcv[row]*ML + lane4;
                atomicMax(ab+0, fenc(v0));
                atomicMax(ab+1, fenc(v1));
                atomicMax(ab+2, fenc(v2));
                atomicMax(ab+3, fenc(v3));
            }
        }
    }
}

// ---------------- elementwise / segment kernels ----------------
__global__ void k_hstar(const float* __restrict__ x, float* __restrict__ h){
    int n = blockIdx.x*blockDim.x + threadIdx.x;
    if (n < NN) h[n] = x[2*n];
}
__global__ void k_copy(const float* __restrict__ a, float* __restrict__ b, int n){
    int i = blockIdx.x*blockDim.x + threadIdx.x;
    if (i < n) b[i] = a[i];
}
__global__ void k_zero(float* __restrict__ p, int n){
    int i = blockIdx.x*blockDim.x + threadIdx.x;
    if (i < n) p[i] = 0.f;
}
__global__ void k_fill_u(unsigned* __restrict__ p, unsigned v, int n){
    int i = blockIdx.x*blockDim.x + threadIdx.x;
    if (i < n) p[i] = v;
}
__global__ void k_flows(const float* __restrict__ h, const float* __restrict__ r,
                        const int* __restrict__ s, const int* __restrict__ rc,
                        float* __restrict__ q){
    int e = blockIdx.x*blockDim.x + threadIdx.x;
    if (e >= EE) return;
    float dh = h[s[e]] - h[rc[e]];
    q[e] = signf(dh) * __powf((fabsf(dh) + ZETA) / (r[e] + ZETA), INVP);
}
__global__ void k_segsum(const float* __restrict__ q, const int* __restrict__ rc,
                         float* __restrict__ d){
    int e = blockIdx.x*blockDim.x + threadIdx.x;
    if (e < EE) atomicAdd(&d[rc[e]], q[e]);
}
__global__ void k_node_in(const float* __restrict__ dh, const float* __restrict__ x,
                          const float* __restrict__ W, float* __restrict__ g){
    int idx = blockIdx.x*blockDim.x + threadIdx.x;
    if (idx >= NN*ML) return;
    int n = idx >> 7, j = idx & 127;
    g[idx] = selu_f(dh[n]) * W[j] + selu_f(x[2*n+1]) * W[ML + j];
}
__global__ void k_edge_in(const float* __restrict__ qt, const float* __restrict__ qh,
                          const float* __restrict__ W, float* __restrict__ z){
    long idx = (long)blockIdx.x*blockDim.x + threadIdx.x;
    if (idx >= (long)EE*ML) return;
    int e = (int)(idx >> 7), j = (int)(idx & 127);
    z[idx] = selu_f(qt[e]) * W[j] + selu_f(qh[e]) * W[ML + j];
}
__global__ void k_antisym(float* __restrict__ q){
    int idx = blockIdx.x*blockDim.x + threadIdx.x;
    if (idx >= BC*E2C) return;
    int b = idx / E2C, i = idx % E2C;
    q[b*EPGC + E2C + i] = -q[b*EPGC + i];
}
__global__ void k_hl(const float* __restrict__ q, const float* __restrict__ r,
                     float* __restrict__ hl){
    int e = blockIdx.x*blockDim.x + threadIdx.x;
    if (e >= EE) return;
    float qe = q[e];
    float aq = fabsf(qe);
    float p  = (aq < 1e-30f) ? 0.f : __powf(aq, PEXP);
    hl[e] = r[e] * signf(qe) * p;
}
__global__ void k_head_edge(const float* __restrict__ h, const float* __restrict__ hl,
                            const int* __restrict__ s, const int* __restrict__ rc,
                            unsigned* __restrict__ agg){
    int e = blockIdx.x*blockDim.x + threadIdx.x;
    if (e < EE) atomicMax(&agg[rc[e]], fenc(h[s[e]] - hl[e]));
}
__global__ void k_head_node(const unsigned* __restrict__ agg, const float* __restrict__ hold,
                            const float* __restrict__ x, float* __restrict__ hnew){
    int n = blockIdx.x*blockDim.x + threadIdx.x;
    if (n >= NN) return;
    float hs = x[2*n];
    unsigned u = agg[n];
    float a = (u == ENC_NEGINF) ? -INFINITY : fdec(u);
    hnew[n] = (hs != 0.f) ? hs : fmaxf(hold[n], a);
}

// ---------------- host orchestration ----------------
template<typename T>
static T* sym_addr(const void* sym){
    void* p = nullptr;
    cudaGetSymbolAddress(&p, sym);
    return (T*)p;
}

extern "C" void kernel_launch(void* const* d_in, const int* in_sizes, int n_in,
                              void* d_out, int out_size)
{
    const float* x    = (const float*)d_in[0];
    const float* r    = (const float*)d_in[1];
    const float* Wni  = (const float*)d_in[2];
    const float* Wei  = (const float*)d_in[3];
    const float* Wf1  = (const float*)d_in[4];
    const float* Wf2  = (const float*)d_in[5];
    const float* Wf3  = (const float*)d_in[6];
    const float* We1  = (const float*)d_in[7];
    const float* We2  = (const float*)d_in[8];
    const float* Wn1  = (const float*)d_in[9];
    const float* Wn2  = (const float*)d_in[10];
    const int*   sndr = (const int*)d_in[11];
    const int*   rcvr = (const int*)d_in[12];
    float*       out  = (float*)d_out;

    float*    g   = sym_addr<float>(g_buf);
    unsigned* agu = sym_addr<unsigned>(agg_buf);
    float*    tN  = sym_addr<float>(tN_buf);
    float*    u   = sym_addr<float>(u_buf);
    float*    v   = sym_addr<float>(v_buf);
    float*    z   = sym_addr<float>(z_buf);
    float*    w   = sym_addr<float>(w_buf);
    float*    qh  = sym_addr<float>(qh_buf);
    float*    qt  = sym_addr<float>(qt_buf);
    float*    hl  = sym_addr<float>(hl_buf);
    float*    dh  = sym_addr<float>(dh_buf);
    float*    hA  = sym_addr<float>(hA_buf);
    float*    hB  = sym_addr<float>(hB_buf);
    unsigned* agS = sym_addr<unsigned>(aggS_buf);

    const int T = 256;
    const int gN  = (NN + T - 1) / T;
    const int gE  = (EE + T - 1) / T;
    const int gNM = (NN*ML + T - 1) / T;
    const long EM = (long)EE*ML;
    const int gEM = (int)((EM + T - 1) / T);

    const dim3 GE((EE + 127)/128, 1);      // 1000
    const dim3 GNo((NN + 127)/128, 1);     // 313
    const dim3 GN2((NN + 127)/128, 2);     // u/v pair

    // ---- initial flows ----
    k_hstar<<<gN, T>>>(x, hA);
    k_flows<<<gE, T>>>(hA, r, sndr, rcvr, qh);
    k_zero<<<gN, T>>>(dh, NN);
    k_segsum<<<gE, T>>>(qh, rcvr, dh);
    k_copy<<<gE, T>>>(qh, qt, EE);

    for (int k = 0; k < K_ITERS; k++){
        k_node_in<<<gNM, T>>>(dh, x, Wni, g);
        k_edge_in<<<gEM, T>>>(qt, qh, Wei, z);

        for (int i = 0; i < I_LAYERS; i++){
            const float* We1i = We1 + (size_t)i*384*ML;
            // u = selu(g)@We1[0:128], v = selu(g)@We1[128:256]
            gemm2<128,M_SELU,false,false,false><<<GN2,256>>>(
                g,nullptr,nullptr,nullptr, nullptr,nullptr,
                We1i, u, v, nullptr,nullptr, nullptr,nullptr, NN);
            // w = selu(z)@We1[256:384]
            gemm2<128,M_SELU,false,false,false><<<GE,256>>>(
                z,nullptr,nullptr,nullptr, nullptr,nullptr,
                We1i + 256*ML, w, nullptr, nullptr,nullptr, nullptr,nullptr, EE);
            // z = selu(u[s]+v[r]+w) @ We2  (+ fused segment-max into agu)
            k_fill_u<<<gNM, T>>>(agu, ENC_NEGINF, NN*ML);
            gemm2<128,M_SUM3,false,true,false><<<GE,256>>>(
                u, v, w, nullptr, sndr, rcvr,
                We2 + (size_t)i*ML*ML, z, nullptr, agu, rcvr, nullptr,nullptr, EE);
            // tN = selu([selu(g), selu(dec(agu))] @ Wn1)
            gemm2<256,M_CAT2D,true,false,false><<<GNo,256>>>(
                g,nullptr,nullptr, agu, nullptr,nullptr,
                Wn1 + (size_t)i*256*ML, tN, nullptr, nullptr,nullptr, nullptr,nullptr, NN);
            // g = tN @ Wn2
            gemm2<128,M_PLAIN,false,false,false><<<GNo,256>>>(
                tN,nullptr,nullptr,nullptr, nullptr,nullptr,
                Wn2 + (size_t)i*ML*ML, g, nullptr, nullptr,nullptr, nullptr,nullptr, NN);
        }

        // flow head: q_hat += selu(selu(selu(lam)@Wf1)@Wf2)@Wf3 with lam split
        gemm2<128,M_SELU,false,false,false><<<GN2,256>>>(
            g,nullptr,nullptr,nullptr, nullptr,nullptr,
            Wf1, u, v, nullptr,nullptr, nullptr,nullptr, NN);
        gemm2<128,M_SELU,false,false,false><<<GE,256>>>(
            z,nullptr,nullptr,nullptr, nullptr,nullptr,
            Wf1 + 256*ML, w, nullptr, nullptr,nullptr, nullptr,nullptr, EE);
        gemm2<128,M_SUM3,true,false,true><<<GE,256>>>(
            u, v, w, nullptr, sndr, rcvr,
            Wf2, nullptr, nullptr, nullptr,nullptr, Wf3, qh, EE);
        k_antisym<<<(BC*E2C + T - 1)/T, T>>>(qh);

        // d_hat = segment_sum(q_hat)
        k_zero<<<gN, T>>>(dh, NN);
        k_segsum<<<gE, T>>>(qh, rcvr, dh);

        // h_tilde = construct_heads(h_star, q_hat)
        k_hstar<<<gN, T>>>(x, hA);
        k_hl<<<gE, T>>>(qh, r, hl);
        float* hc = hA; float* hn = hB;
        for (int j = 0; j < J_HEADS; j++){
            k_fill_u<<<gN, T>>>(agS, ENC_NEGINF, NN);
            k_head_edge<<<gE, T>>>(hc, hl, sndr, rcvr, agS);
            k_head_node<<<gN, T>>>(agS, hc, x, hn);
            float* t2 = hc; hc = hn; hn = t2;
        }
        // J_HEADS even -> result in hA

        k_flows<<<gE, T>>>(hc, r, sndr, rcvr, qt);
    }

    k_copy<<<gN, T>>>(hA, out, NN);
    (void)in_sizes; (void)n_in; (void)out_size;
}

// round 5
// speedup vs baseline: 1.5518x; 1.2940x over previous
#include <cuda_runtime.h>
#include <cuda_bf16.h>
#include <math.h>
#include <stdint.h>

// ---------------- problem constants ----------------
#define NN   40000
#define EE   128000
#define E2C  16000
#define EPGC 32000
#define BC   4
#define ML   128
#define ZETA 1e-6f
#define PEXP 1.852f
#define INVP (1.0f/1.852f)
#define I_LAYERS 3
#define K_ITERS  4
#define J_HEADS  6

#define SELU_SCALE 1.0507009873554805f
#define SELU_ALPHA 1.6732632423543772f
#define ENC_NEGINF 0x007FFFFFu

// A tile in smem: 128 rows x 136 (padded) bf16, hi + lo
#define AST 136
#define SM_ALO_OFF (128*AST)          // in halves
#define SM_TOT (2*128*AST*2)          // bytes = 69632

// ---------------- device scratch ----------------
__device__ float    g_buf[NN*ML];
__device__ unsigned agg_buf[NN*ML];
__device__ float    tN_buf[NN*ML];
__device__ float    u_buf[NN*ML];
__device__ float    v_buf[NN*ML];
__device__ float    z_buf[(size_t)EE*ML];
__device__ float    w_buf[(size_t)EE*ML];
__device__ float    qh_buf[EE];
__device__ float    qt_buf[EE];
__device__ float    hl_buf[EE];
__device__ float    dh_buf[NN];
__device__ float    hA_buf[NN];
__device__ float    hB_buf[NN];
__device__ unsigned aggS_buf[NN];
// weight chunks in mma-fragment order: per chunk 8 kchunks x 16 ntiles x 32 lanes x 2 words
__device__ unsigned short whi_buf[25*16384];
__device__ unsigned short wlo_buf[25*16384];

// ---------------- scalar helpers ----------------
__device__ __forceinline__ float selu_f(float x){
    return x > 0.f ? SELU_SCALE * x : SELU_SCALE * SELU_ALPHA * (__expf(x) - 1.f);
}
__device__ __forceinline__ unsigned fenc(float f){
    unsigned u = __float_as_uint(f);
    return (u >> 31) ? ~u : (u | 0x80000000u);
}
__device__ __forceinline__ float fdec(unsigned u){
    return (u >> 31) ? __uint_as_float(u & 0x7fffffffu) : __uint_as_float(~u);
}
__device__ __forceinline__ float signf(float x){
    return (x > 0.f) ? 1.f : ((x < 0.f) ? -1.f : 0.f);
}
__device__ __forceinline__ void mma16816(float* d, const unsigned* a, unsigned b0, unsigned b1){
    asm volatile("mma.sync.aligned.m16n8k16.row.col.f32.bf16.bf16.f32 "
        "{%0,%1,%2,%3}, {%4,%5,%6,%7}, {%8,%9}, {%0,%1,%2,%3};"
        : "+f"(d[0]), "+f"(d[1]), "+f"(d[2]), "+f"(d[3])
        : "r"(a[0]), "r"(a[1]), "r"(a[2]), "r"(a[3]), "r"(b0), "r"(b1));
}
__device__ __forceinline__ void ld16(const float* p, float* v){
    #pragma unroll
    for (int i = 0; i < 4; i++){
        float4 t = *(const float4*)(p + 4*i);
        v[4*i]=t.x; v[4*i+1]=t.y; v[4*i+2]=t.z; v[4*i+3]=t.w;
    }
}
__device__ __forceinline__ void split_pack(const float* vals, unsigned* hi2, unsigned* lo2){
    #pragma unroll
    for (int j = 0; j < 8; j++){
        float a = vals[2*j], b = vals[2*j+1];
        __nv_bfloat16 ha = __float2bfloat16_rn(a);
        __nv_bfloat16 hb = __float2bfloat16_rn(b);
        float ra = a - __bfloat162float(ha);
        float rb = b - __bfloat162float(hb);
        __nv_bfloat162 hp = __halves2bfloat162(ha, hb);
        __nv_bfloat162 lp = __halves2bfloat162(__float2bfloat16_rn(ra), __float2bfloat16_rn(rb));
        hi2[j] = *reinterpret_cast<unsigned*>(&hp);
        lo2[j] = *reinterpret_cast<unsigned*>(&lp);
    }
}

// ---------------- weight prep: fp32 [128,128] -> fragment-ordered bf16 hi/lo ----------------
// B[k][n] fragment mapping (m16n8k16 col-major B):
//   word = ((kc*16 + nt)*32 + lane)*2 + r ; half h
//   k = kc*16 + r*8 + q*2 + h, q = lane&3 ; n = nt*8 + lane>>2
__global__ void k_prep(const float* __restrict__ W, int nK, int matStride, int chunk0){
    int c = blockIdx.x;
    int mat = c / nK, kb = c % nK;
    const float* src = W + (size_t)mat*matStride + (size_t)kb*128*128;
    unsigned short* dh = whi_buf + (size_t)(chunk0 + c)*16384;
    unsigned short* dl = wlo_buf + (size_t)(chunk0 + c)*16384;
    for (int idx = threadIdx.x; idx < 16384; idx += blockDim.x){
        int k = idx >> 7, n = idx & 127;
        float vv = src[(size_t)k*128 + n];
        __nv_bfloat16 h = __float2bfloat16_rn(vv);
        float rr = vv - __bfloat162float(h);
        __nv_bfloat16 l = __float2bfloat16_rn(rr);
        int kc = k >> 4, kk = k & 15;
        int r = kk >> 3, q = (kk >> 1) & 3, hh = kk & 1;
        int nt = n >> 3, lane = ((n & 7) << 2) + q;
        int half = (((kc*16 + nt)*32 + lane)*2 + r)*2 + hh;
        dh[half] = *reinterpret_cast<unsigned short*>(&h);
        dl[half] = *reinterpret_cast<unsigned short*>(&l);
    }
}

// ---------------- tensor-core GEMM: C[M x 128] = act(A'[M x K] @ Wt) ----------------
enum { M_PLAIN=0, M_SELU=1, M_SUM3=2, M_CAT2D=3 };

template<int NCHUNK, int MODE, bool OUTACT, bool AGGMAX, bool DOTOUT>
__global__ void __launch_bounds__(256) tcg(
    const float* __restrict__ A0, const float* __restrict__ A1,
    const float* __restrict__ A2, const unsigned* __restrict__ AU,
    const int* __restrict__ iS, const int* __restrict__ iR,
    const unsigned short* __restrict__ Bhi, const unsigned short* __restrict__ Blo,
    float* __restrict__ C, float* __restrict__ C2,
    unsigned* __restrict__ aggU, const int* __restrict__ rcv,
    const float* __restrict__ Wf3, float* __restrict__ qout, int M)
{
    extern __shared__ unsigned short As[];   // hi at 0, lo at SM_ALO_OFF (halves)
    const int tid = threadIdx.x, wid = tid >> 5, lane = tid & 31;
    const int row0 = blockIdx.x * 128;
    if (blockIdx.y){ Bhi += (size_t)NCHUNK*16384; Blo += (size_t)NCHUNK*16384; C = C2; }

    const int mq = wid & 3;     // M quad: rows mq*32 + [0,32)
    const int nh = wid >> 2;    // N half: cols nh*64 + [0,64)

    float acc[2][8][4];
    #pragma unroll
    for (int i = 0; i < 2; i++)
        #pragma unroll
        for (int j = 0; j < 8; j++)
            #pragma unroll
            for (int t = 0; t < 4; t++) acc[i][j][t] = 0.f;

    #pragma unroll 1
    for (int ch = 0; ch < NCHUNK; ch++){
        // ---- stage A chunk: gather + selu + bf16 split into smem ----
        #pragma unroll 1
        for (int p = 0; p < 4; p++){
            int m  = p*32 + (tid >> 3);
            int c0 = (tid & 7) * 16;
            int grow = row0 + m; if (grow > M-1) grow = M-1;
            float vals[16];
            if (MODE == M_SUM3){
                const float* pa = A0 + (size_t)iS[grow]*ML + c0;
                const float* pb = A1 + (size_t)iR[grow]*ML + c0;
                const float* pc = A2 + (size_t)grow*ML + c0;
                float va[16], vb[16], vc[16];
                ld16(pa, va); ld16(pb, vb); ld16(pc, vc);
                #pragma unroll
                for (int j = 0; j < 16; j++) vals[j] = selu_f(va[j] + vb[j] + vc[j]);
            } else if (MODE == M_SELU){
                ld16(A0 + (size_t)grow*ML + c0, vals);
                #pragma unroll
                for (int j = 0; j < 16; j++) vals[j] = selu_f(vals[j]);
            } else if (MODE == M_PLAIN){
                ld16(A0 + (size_t)grow*ML + c0, vals);
            } else { // M_CAT2D
                if (ch == 0){
                    ld16(A0 + (size_t)grow*ML + c0, vals);
                    #pragma unroll
                    for (int j = 0; j < 16; j++) vals[j] = selu_f(vals[j]);
                } else {
                    const unsigned* pu = AU + (size_t)grow*ML + c0;
                    #pragma unroll
                    for (int i = 0; i < 4; i++){
                        uint4 t = *(const uint4*)(pu + 4*i);
                        unsigned uu[4] = {t.x, t.y, t.z, t.w};
                        #pragma unroll
                        for (int j = 0; j < 4; j++){
                            float d = (uu[j] == ENC_NEGINF) ? 0.f : fdec(uu[j]);
                            vals[4*i + j] = selu_f(d);
                        }
                    }
                }
            }
            unsigned hi2[8], lo2[8];
            split_pack(vals, hi2, lo2);
            unsigned short* ph = As + m*AST + c0;
            unsigned short* pl = ph + SM_ALO_OFF;
            *(uint4*)(ph)     = make_uint4(hi2[0], hi2[1], hi2[2], hi2[3]);
            *(uint4*)(ph + 8) = make_uint4(hi2[4], hi2[5], hi2[6], hi2[7]);
            *(uint4*)(pl)     = make_uint4(lo2[0], lo2[1], lo2[2], lo2[3]);
            *(uint4*)(pl + 8) = make_uint4(lo2[4], lo2[5], lo2[6], lo2[7]);
        }
        __syncthreads();

        // ---- compute: 8 k-chunks, per warp 2 m-tiles x 8 n-tiles, 3 products ----
        const unsigned* BHw = (const unsigned*)Bhi + (size_t)ch*8192;
        const unsigned* BLw = (const unsigned*)Blo + (size_t)ch*8192;
        const int arow = mq*32 + (lane >> 2);
        const int acol = (lane & 3) * 2;
        #pragma unroll 1
        for (int kc = 0; kc < 8; kc++){
            unsigned ah[2][4], al[2][4];
            #pragma unroll
            for (int i = 0; i < 2; i++){
                const unsigned short* base = As + (arow + i*16)*AST + kc*16 + acol;
                ah[i][0] = *(const unsigned*)(base);
                ah[i][1] = *(const unsigned*)(base + 8*AST);
                ah[i][2] = *(const unsigned*)(base + 8);
                ah[i][3] = *(const unsigned*)(base + 8*AST + 8);
                const unsigned short* basel = base + SM_ALO_OFF;
                al[i][0] = *(const unsigned*)(basel);
                al[i][1] = *(const unsigned*)(basel + 8*AST);
                al[i][2] = *(const unsigned*)(basel + 8);
                al[i][3] = *(const unsigned*)(basel + 8*AST + 8);
            }
            #pragma unroll
            for (int j = 0; j < 8; j++){
                int nt = nh*8 + j;
                size_t widx = (size_t)((kc*16 + nt)*32 + lane)*2;
                uint2 bh = *(const uint2*)(BHw + widx);
                uint2 bl = *(const uint2*)(BLw + widx);
                #pragma unroll
                for (int i = 0; i < 2; i++){
                    mma16816(acc[i][j], ah[i], bh.x, bh.y);
                    mma16816(acc[i][j], ah[i], bl.x, bl.y);
                    mma16816(acc[i][j], al[i], bh.x, bh.y);
                }
            }
        }
        __syncthreads();
    }

    // ---- epilogue from register fragments ----
    // thread owns rows: row0 + mq*32 + lane/4 + i*16 + h*8 ; cols: nh*64 + j*8 + (lane&3)*2 + {0,1}
    const int rbase = row0 + mq*32 + (lane >> 2);
    const int cbase = nh*64 + (lane & 3)*2;
    #pragma unroll
    for (int i = 0; i < 2; i++){
        #pragma unroll
        for (int h = 0; h < 2; h++){
            int row = rbase + i*16 + h*8;
            if (row >= M) continue;
            float f[16];
            #pragma unroll
            for (int j = 0; j < 8; j++){
                f[2*j]   = acc[i][j][2*h];
                f[2*j+1] = acc[i][j][2*h+1];
                if (OUTACT){ f[2*j] = selu_f(f[2*j]); f[2*j+1] = selu_f(f[2*j+1]); }
            }
            if (DOTOUT){
                float s = 0.f;
                #pragma unroll
                for (int j = 0; j < 8; j++){
                    float2 wv = *(const float2*)(Wf3 + cbase + j*8);
                    s += f[2*j]*wv.x + f[2*j+1]*wv.y;
                }
                s += __shfl_xor_sync(0xffffffffu, s, 1);
                s += __shfl_xor_sync(0xffffffffu, s, 2);
                // row's 128 cols are split across the two nh warps -> must combine atomically
                if ((lane & 3) == 0) atomicAdd(qout + row, s);
            } else {
                float* cp = C + (size_t)row*ML + cbase;
                #pragma unroll
                for (int j = 0; j < 8; j++)
                    *(float2*)(cp + j*8) = make_float2(f[2*j], f[2*j+1]);
                if (AGGMAX){
                    unsigned* ap = aggU + (size_t)rcv[row]*ML + cbase;
                    #pragma unroll
                    for (int j = 0; j < 8; j++){
                        atomicMax(ap + j*8,     fenc(f[2*j]));
                        atomicMax(ap + j*8 + 1, fenc(f[2*j+1]));
                    }
                }
            }
        }
    }
}

// ---------------- elementwise / segment kernels ----------------
__global__ void k_hstar(const float* __restrict__ x, float* __restrict__ h){
    int n = blockIdx.x*blockDim.x + threadIdx.x;
    if (n < NN) h[n] = x[2*n];
}
__global__ void k_copy(const float* __restrict__ a, float* __restrict__ b, int n){
    int i = blockIdx.x*blockDim.x + threadIdx.x;
    if (i < n) b[i] = a[i];
}
__global__ void k_zero(float* __restrict__ p, int n){
    int i = blockIdx.x*blockDim.x + threadIdx.x;
    if (i < n) p[i] = 0.f;
}
__global__ void k_fill_u(unsigned* __restrict__ p, unsigned v, int n){
    int i = blockIdx.x*blockDim.x + threadIdx.x;
    if (i < n) p[i] = v;
}
__global__ void k_flows(const float* __restrict__ h, const float* __restrict__ r,
                        const int* __restrict__ s, const int* __restrict__ rc,
                        float* __restrict__ q){
    int e = blockIdx.x*blockDim.x + threadIdx.x;
    if (e >= EE) return;
    float dh = h[s[e]] - h[rc[e]];
    q[e] = signf(dh) * __powf((fabsf(dh) + ZETA) / (r[e] + ZETA), INVP);
}
__global__ void k_segsum(const float* __restrict__ q, const int* __restrict__ rc,
                         float* __restrict__ d){
    int e = blockIdx.x*blockDim.x + threadIdx.x;
    if (e < EE) atomicAdd(&d[rc[e]], q[e]);
}
__global__ void k_node_in(const float* __restrict__ dh, const float* __restrict__ x,
                          const float* __restrict__ W, float* __restrict__ g){
    int idx = blockIdx.x*blockDim.x + threadIdx.x;
    if (idx >= NN*ML) return;
    int n = idx >> 7, j = idx & 127;
    g[idx] = selu_f(dh[n]) * W[j] + selu_f(x[2*n+1]) * W[ML + j];
}
__global__ void k_edge_in(const float* __restrict__ qt, const float* __restrict__ qh,
                          const float* __restrict__ W, float* __restrict__ z){
    long idx = (long)blockIdx.x*blockDim.x + threadIdx.x;
    if (idx >= (long)EE*ML) return;
    int e = (int)(idx >> 7), j = (int)(idx & 127);
    z[idx] = selu_f(qt[e]) * W[j] + selu_f(qh[e]) * W[ML + j];
}
__global__ void k_antisym(float* __restrict__ q){
    int idx = blockIdx.x*blockDim.x + threadIdx.x;
    if (idx >= BC*E2C) return;
    int b = idx / E2C, i = idx % E2C;
    q[b*EPGC + E2C + i] = -q[b*EPGC + i];
}
__global__ void k_hl(const float* __restrict__ q, const float* __restrict__ r,
                     float* __restrict__ hl){
    int e = blockIdx.x*blockDim.x + threadIdx.x;
    if (e >= EE) return;
    float qe = q[e];
    float aq = fabsf(qe);
    float p  = (aq < 1e-30f) ? 0.f : __powf(aq, PEXP);
    hl[e] = r[e] * signf(qe) * p;
}
__global__ void k_head_edge(const float* __restrict__ h, const float* __restrict__ hl,
                            const int* __restrict__ s, const int* __restrict__ rc,
                            unsigned* __restrict__ agg){
    int e = blockIdx.x*blockDim.x + threadIdx.x;
    if (e < EE) atomicMax(&agg[rc[e]], fenc(h[s[e]] - hl[e]));
}
__global__ void k_head_node(const unsigned* __restrict__ agg, const float* __restrict__ hold,
                            const float* __restrict__ x, float* __restrict__ hnew){
    int n = blockIdx.x*blockDim.x + threadIdx.x;
    if (n >= NN) return;
    float hs = x[2*n];
    unsigned u = agg[n];
    float a = (u == ENC_NEGINF) ? -INFINITY : fdec(u);
    hnew[n] = (hs != 0.f) ? hs : fmaxf(hold[n], a);
}

// ---------------- host orchestration ----------------
template<typename T>
static T* sym_addr(const void* sym){
    void* p = nullptr;
    cudaGetSymbolAddress(&p, sym);
    return (T*)p;
}
static void set_smem(const void* f){
    cudaFuncSetAttribute(f, cudaFuncAttributeMaxDynamicSharedMemorySize, SM_TOT);
}

extern "C" void kernel_launch(void* const* d_in, const int* in_sizes, int n_in,
                              void* d_out, int out_size)
{
    const float* x    = (const float*)d_in[0];
    const float* r    = (const float*)d_in[1];
    const float* Wni  = (const float*)d_in[2];
    const float* Wei  = (const float*)d_in[3];
    const float* Wf1  = (const float*)d_in[4];
    const float* Wf2  = (const float*)d_in[5];
    const float* Wf3  = (const float*)d_in[6];
    const float* We1  = (const float*)d_in[7];
    const float* We2  = (const float*)d_in[8];
    const float* Wn1  = (const float*)d_in[9];
    const float* Wn2  = (const float*)d_in[10];
    const int*   sndr = (const int*)d_in[11];
    const int*   rcvr = (const int*)d_in[12];
    float*       out  = (float*)d_out;

    float*    g   = sym_addr<float>(g_buf);
    unsigned* agu = sym_addr<unsigned>(agg_buf);
    float*    tN  = sym_addr<float>(tN_buf);
    float*    u   = sym_addr<float>(u_buf);
    float*    v   = sym_addr<float>(v_buf);
    float*    z   = sym_addr<float>(z_buf);
    float*    w   = sym_addr<float>(w_buf);
    float*    qh  = sym_addr<float>(qh_buf);
    float*    qt  = sym_addr<float>(qt_buf);
    float*    hl  = sym_addr<float>(hl_buf);
    float*    dh  = sym_addr<float>(dh_buf);
    float*    hA  = sym_addr<float>(hA_buf);
    float*    hB  = sym_addr<float>(hB_buf);
    unsigned* agS = sym_addr<unsigned>(aggS_buf);
    unsigned short* WH = sym_addr<unsigned short>(whi_buf);
    unsigned short* WL = sym_addr<unsigned short>(wlo_buf);

    set_smem((const void*)tcg<1,M_SELU ,false,false,false>);
    set_smem((const void*)tcg<1,M_SUM3 ,false,true ,false>);
    set_smem((const void*)tcg<2,M_CAT2D,true ,false,false>);
    set_smem((const void*)tcg<1,M_PLAIN,false,false,false>);
    set_smem((const void*)tcg<1,M_SUM3 ,true ,false,true >);

    const int T = 256;
    const int gN  = (NN + T - 1) / T;
    const int gE  = (EE + T - 1) / T;
    const int gNM = (NN*ML + T - 1) / T;
    const long EM = (long)EE*ML;
    const int gEM = (int)((EM + T - 1) / T);

    const int  TE = (EE + 127)/128;          // 1000 edge tiles
    const int  TN = (NN + 127)/128;          // 313 node tiles
    const dim3 GN2(TN, 2);

    #define CHK(i) (WH + (size_t)(i)*16384), (WL + (size_t)(i)*16384)

    // ---- weight prep ----
    // We1: 0..8 | We2: 9..11 | Wn1: 12..17 | Wn2: 18..20 | Wf1: 21..23 | Wf2: 24
    k_prep<<<9, 256>>>(We1, 3, 384*ML, 0);
    k_prep<<<3, 256>>>(We2, 1, ML*ML, 9);
    k_prep<<<6, 256>>>(Wn1, 2, 256*ML, 12);
    k_prep<<<3, 256>>>(Wn2, 1, ML*ML, 18);
    k_prep<<<3, 256>>>(Wf1, 3, 0, 21);
    k_prep<<<1, 256>>>(Wf2, 1, 0, 24);

    // ---- initial flows ----
    k_hstar<<<gN, T>>>(x, hA);
    k_flows<<<gE, T>>>(hA, r, sndr, rcvr, qh);
    k_zero<<<gN, T>>>(dh, NN);
    k_segsum<<<gE, T>>>(qh, rcvr, dh);
    k_copy<<<gE, T>>>(qh, qt, EE);

    for (int k = 0; k < K_ITERS; k++){
        k_node_in<<<gNM, T>>>(dh, x, Wni, g);
        k_edge_in<<<gEM, T>>>(qt, qh, Wei, z);

        for (int i = 0; i < I_LAYERS; i++){
            // u = selu(g)@We1[0:128], v = selu(g)@We1[128:256]
            tcg<1,M_SELU,false,false,false><<<GN2, 256, SM_TOT>>>(
                g, nullptr, nullptr, nullptr, nullptr, nullptr,
                CHK(i*3), u, v, nullptr, nullptr, nullptr, nullptr, NN);
            // w = selu(z)@We1[256:384]
            tcg<1,M_SELU,false,false,false><<<TE, 256, SM_TOT>>>(
                z, nullptr, nullptr, nullptr, nullptr, nullptr,
                CHK(i*3+2), w, nullptr, nullptr, nullptr, nullptr, nullptr, EE);
            // z = selu(u[s]+v[r]+w) @ We2  (+ fused segment-max)
            k_fill_u<<<gNM, T>>>(agu, ENC_NEGINF, NN*ML);
            tcg<1,M_SUM3,false,true,false><<<TE, 256, SM_TOT>>>(
                u, v, w, nullptr, sndr, rcvr,
                CHK(9+i), z, nullptr, agu, rcvr, nullptr, nullptr, EE);
            // tN = selu([selu(g), selu(dec(agu))] @ Wn1)
            tcg<2,M_CAT2D,true,false,false><<<TN, 256, SM_TOT>>>(
                g, nullptr, nullptr, agu, nullptr, nullptr,
                CHK(12+2*i), tN, nullptr, nullptr, nullptr, nullptr, nullptr, NN);
            // g = tN @ Wn2
            tcg<1,M_PLAIN,false,false,false><<<TN, 256, SM_TOT>>>(
                tN, nullptr, nullptr, nullptr, nullptr, nullptr,
                CHK(18+i), g, nullptr, nullptr, nullptr, nullptr, nullptr, NN);
        }

        // flow head
        tcg<1,M_SELU,false,false,false><<<GN2, 256, SM_TOT>>>(
            g, nullptr, nullptr, nullptr, nullptr, nullptr,
            CHK(21), u, v, nullptr, nullptr, nullptr, nullptr, NN);
        tcg<1,M_SELU,false,false,false><<<TE, 256, SM_TOT>>>(
            z, nullptr, nullptr, nullptr, nullptr, nullptr,
            CHK(23), w, nullptr, nullptr, nullptr, nullptr, nullptr, EE);
        tcg<1,M_SUM3,true,false,true><<<TE, 256, SM_TOT>>>(
            u, v, w, nullptr, sndr, rcvr,
            CHK(24), nullptr, nullptr, nullptr, nullptr, Wf3, qh, EE);
        k_antisym<<<(BC*E2C + T - 1)/T, T>>>(qh);

        // d_hat
        k_zero<<<gN, T>>>(dh, NN);
        k_segsum<<<gE, T>>>(qh, rcvr, dh);

        // construct_heads
        k_hstar<<<gN, T>>>(x, hA);
        k_hl<<<gE, T>>>(qh, r, hl);
        float* hc = hA; float* hn = hB;
        for (int j = 0; j < J_HEADS; j++){
            k_fill_u<<<gN, T>>>(agS, ENC_NEGINF, NN);
            k_head_edge<<<gE, T>>>(hc, hl, sndr, rcvr, agS);
            k_head_node<<<gN, T>>>(agS, hc, x, hn);
            float* t2 = hc; hc = hn; hn = t2;
        }

        k_flows<<<gE, T>>>(hc, r, sndr, rcvr, qt);
    }

    k_copy<<<gN, T>>>(hA, out, NN);
    (void)in_sizes; (void)n_in; (void)out_size;
    #undef CHK
}

// round 6
// speedup vs baseline: 2.2872x; 1.4739x over previous
#include <cuda_runtime.h>
#include <cuda_bf16.h>
#include <math.h>
#include <stdint.h>

// ---------------- problem constants ----------------
#define NN   40000
#define EE   128000
#define E2C  16000
#define EPGC 32000
#define BC   4
#define ML   128
#define ZETA 1e-6f
#define PEXP 1.852f
#define INVP (1.0f/1.852f)
#define I_LAYERS 3
#define K_ITERS  4
#define J_HEADS  6

#define SELU_SCALE 1.0507009873554805f
#define SELU_ALPHA 1.6732632423543772f
#define ENC_NEGINF 0x007FFFFFu

// A tile in smem: 128 rows x 136 (padded) bf16, hi + lo
#define AST 136
#define SM_ALO_OFF (128*AST)          // in halves
#define SM_TOT (2*128*AST*2)          // bytes = 69632

// ---------------- device scratch ----------------
__device__ float    g_buf[NN*ML];
__device__ unsigned agg_buf[NN*ML];
__device__ float    tN_buf[NN*ML];
__device__ float    u_buf[NN*ML];
__device__ float    v_buf[NN*ML];
__device__ float    z_buf[(size_t)EE*ML];
__device__ float    w_buf[(size_t)EE*ML];
__device__ float    qh_buf[EE];
__device__ float    qt_buf[EE];
__device__ float    hl_buf[EE];
__device__ float    dh_buf[NN];
__device__ float    hA_buf[NN];
__device__ float    hB_buf[NN];
__device__ unsigned aggS_buf[NN];
// weight chunks, fragment order, hi/lo interleaved per uint4:
// uint4 index ((kc*16+nt)*32+lane): {hi_r0, hi_r1, lo_r0, lo_r1}
__device__ unsigned short wpk_buf[(size_t)25*32768];

// ---------------- scalar helpers ----------------
__device__ __forceinline__ float selu_f(float x){
    return x > 0.f ? SELU_SCALE * x : SELU_SCALE * SELU_ALPHA * (__expf(x) - 1.f);
}
__device__ __forceinline__ unsigned fenc(float f){
    unsigned u = __float_as_uint(f);
    return (u >> 31) ? ~u : (u | 0x80000000u);
}
__device__ __forceinline__ float fdec(unsigned u){
    return (u >> 31) ? __uint_as_float(u & 0x7fffffffu) : __uint_as_float(~u);
}
__device__ __forceinline__ float signf(float x){
    return (x > 0.f) ? 1.f : ((x < 0.f) ? -1.f : 0.f);
}
__device__ __forceinline__ void mma16816(float* d, const unsigned* a, unsigned b0, unsigned b1){
    asm volatile("mma.sync.aligned.m16n8k16.row.col.f32.bf16.bf16.f32 "
        "{%0,%1,%2,%3}, {%4,%5,%6,%7}, {%8,%9}, {%0,%1,%2,%3};"
        : "+f"(d[0]), "+f"(d[1]), "+f"(d[2]), "+f"(d[3])
        : "r"(a[0]), "r"(a[1]), "r"(a[2]), "r"(a[3]), "r"(b0), "r"(b1));
}
__device__ __forceinline__ void ldsm_x4(unsigned* r, uint32_t addr){
    asm volatile("ldmatrix.sync.aligned.m8n8.x4.shared.b16 {%0,%1,%2,%3}, [%4];"
        : "=r"(r[0]), "=r"(r[1]), "=r"(r[2]), "=r"(r[3]) : "r"(addr));
}
__device__ __forceinline__ uint32_t smem_u32(const void* p){
    uint32_t a;
    asm("{ .reg .u64 t; cvta.to.shared.u64 t, %1; cvt.u32.u64 %0, t; }" : "=r"(a) : "l"(p));
    return a;
}
__device__ __forceinline__ void ld16(const float* p, float* v){
    #pragma unroll
    for (int i = 0; i < 4; i++){
        float4 t = *(const float4*)(p + 4*i);
        v[4*i]=t.x; v[4*i+1]=t.y; v[4*i+2]=t.z; v[4*i+3]=t.w;
    }
}
__device__ __forceinline__ void split_pack(const float* vals, unsigned* hi2, unsigned* lo2){
    #pragma unroll
    for (int j = 0; j < 8; j++){
        float a = vals[2*j], b = vals[2*j+1];
        __nv_bfloat16 ha = __float2bfloat16_rn(a);
        __nv_bfloat16 hb = __float2bfloat16_rn(b);
        float ra = a - __bfloat162float(ha);
        float rb = b - __bfloat162float(hb);
        __nv_bfloat162 hp = __halves2bfloat162(ha, hb);
        __nv_bfloat162 lp = __halves2bfloat162(__float2bfloat16_rn(ra), __float2bfloat16_rn(rb));
        hi2[j] = *reinterpret_cast<unsigned*>(&hp);
        lo2[j] = *reinterpret_cast<unsigned*>(&lp);
    }
}

// ---------------- weight prep: fp32 [128,128] -> fragment-ordered, hi/lo packed ----------------
__global__ void k_prep(const float* __restrict__ W, int nK, int matStride, int chunk0){
    int c = blockIdx.x;
    int mat = c / nK, kb = c % nK;
    const float* src = W + (size_t)mat*matStride + (size_t)kb*128*128;
    unsigned short* dp = wpk_buf + (size_t)(chunk0 + c)*32768;
    for (int idx = threadIdx.x; idx < 16384; idx += blockDim.x){
        int k = idx >> 7, n = idx & 127;
        float vv = src[(size_t)k*128 + n];
        __nv_bfloat16 h = __float2bfloat16_rn(vv);
        float rr = vv - __bfloat162float(h);
        __nv_bfloat16 l = __float2bfloat16_rn(rr);
        int kc = k >> 4, kk = k & 15;
        int r = kk >> 3, q = (kk >> 1) & 3, hh = kk & 1;
        int nt = n >> 3, lane = ((n & 7) << 2) + q;
        size_t base = ((size_t)((kc*16 + nt)*32 + lane))*8;   // 8 halves per uint4
        dp[base + r*2 + hh]     = *reinterpret_cast<unsigned short*>(&h);  // hi words 0,1
        dp[base + 4 + r*2 + hh] = *reinterpret_cast<unsigned short*>(&l);  // lo words 2,3
    }
}

// ---------------- tensor-core GEMM: C[M x 128] = act(A'[M x K] @ Wt) ----------------
enum { M_PLAIN=0, M_SELU=1, M_SUM3=2, M_CAT2D=3 };

template<int NCHUNK, int MODE, bool OUTACT, bool AGGMAX, bool DOTOUT>
__global__ void __launch_bounds__(256,2) tcg(
    const float* __restrict__ A0, const float* __restrict__ A1,
    const float* __restrict__ A2, const unsigned* __restrict__ AU,
    const int* __restrict__ iS, const int* __restrict__ iR,
    const unsigned short* __restrict__ Bpk,
    float* __restrict__ C, float* __restrict__ C2,
    unsigned* __restrict__ aggU, const int* __restrict__ rcv,
    const float* __restrict__ Wf3, float* __restrict__ qout, int M)
{
    extern __shared__ unsigned short As[];   // hi at 0, lo at SM_ALO_OFF (halves)
    const int tid = threadIdx.x, wid = tid >> 5, lane = tid & 31;
    const int row0 = blockIdx.x * 128;
    if (blockIdx.y){ Bpk += (size_t)NCHUNK*32768; C = C2; }

    const int mq = wid & 1;     // M half: rows mq*64 + [0,64) -> 4 m16 tiles
    const int nh = wid >> 1;    // N quarter: cols nh*32 + [0,32) -> 4 n8 tiles

    // ldmatrix per-thread address components
    const uint32_t sbase = smem_u32(As);
    const uint32_t a_h0 = sbase + ((mq*64 + (lane & 15))*AST + (lane >> 4)*8) * 2;
    const uint32_t a_l0 = a_h0 + SM_ALO_OFF*2;

    float acc[4][4][4];
    #pragma unroll
    for (int i = 0; i < 4; i++)
        #pragma unroll
        for (int j = 0; j < 4; j++)
            #pragma unroll
            for (int t = 0; t < 4; t++) acc[i][j][t] = 0.f;

    #pragma unroll 1
    for (int ch = 0; ch < NCHUNK; ch++){
        // ---- stage A chunk: gather + selu + bf16 split into smem ----
        #pragma unroll 1
        for (int p = 0; p < 4; p++){
            int m  = p*32 + (tid >> 3);
            int c0 = (tid & 7) * 16;
            int grow = row0 + m; if (grow > M-1) grow = M-1;
            float vals[16];
            if (MODE == M_SUM3){
                const float* pa = A0 + (size_t)iS[grow]*ML + c0;
                const float* pb = A1 + (size_t)iR[grow]*ML + c0;
                const float* pc = A2 + (size_t)grow*ML + c0;
                float va[16], vb[16], vc[16];
                ld16(pa, va); ld16(pb, vb); ld16(pc, vc);
                #pragma unroll
                for (int j = 0; j < 16; j++) vals[j] = selu_f(va[j] + vb[j] + vc[j]);
            } else if (MODE == M_SELU){
                ld16(A0 + (size_t)grow*ML + c0, vals);
                #pragma unroll
                for (int j = 0; j < 16; j++) vals[j] = selu_f(vals[j]);
            } else if (MODE == M_PLAIN){
                ld16(A0 + (size_t)grow*ML + c0, vals);
            } else { // M_CAT2D
                if (ch == 0){
                    ld16(A0 + (size_t)grow*ML + c0, vals);
                    #pragma unroll
                    for (int j = 0; j < 16; j++) vals[j] = selu_f(vals[j]);
                } else {
                    const unsigned* pu = AU + (size_t)grow*ML + c0;
                    #pragma unroll
                    for (int i = 0; i < 4; i++){
                        uint4 t = *(const uint4*)(pu + 4*i);
                        unsigned uu[4] = {t.x, t.y, t.z, t.w};
                        #pragma unroll
                        for (int j = 0; j < 4; j++){
                            float d = (uu[j] == ENC_NEGINF) ? 0.f : fdec(uu[j]);
                            vals[4*i + j] = selu_f(d);
                        }
                    }
                }
            }
            unsigned hi2[8], lo2[8];
            split_pack(vals, hi2, lo2);
            unsigned short* ph = As + m*AST + c0;
            unsigned short* pl = ph + SM_ALO_OFF;
            *(uint4*)(ph)     = make_uint4(hi2[0], hi2[1], hi2[2], hi2[3]);
            *(uint4*)(ph + 8) = make_uint4(hi2[4], hi2[5], hi2[6], hi2[7]);
            *(uint4*)(pl)     = make_uint4(lo2[0], lo2[1], lo2[2], lo2[3]);
            *(uint4*)(pl + 8) = make_uint4(lo2[4], lo2[5], lo2[6], lo2[7]);
        }
        __syncthreads();

        // ---- compute: 8 k-chunks, per warp 4 m-tiles x 4 n-tiles, 3 products ----
        const uint4* Bw = (const uint4*)(Bpk + (size_t)ch*32768);
        #pragma unroll 1
        for (int kc = 0; kc < 8; kc++){
            uint4 b[4];
            #pragma unroll
            for (int j = 0; j < 4; j++)
                b[j] = Bw[(size_t)((kc*16 + nh*4 + j)*32 + lane)];
            #pragma unroll
            for (int i = 0; i < 4; i++){
                unsigned ah[4], al[4];
                ldsm_x4(ah, a_h0 + kc*32 + i*(16*AST*2));
                ldsm_x4(al, a_l0 + kc*32 + i*(16*AST*2));
                #pragma unroll
                for (int j = 0; j < 4; j++){
                    mma16816(acc[i][j], ah, b[j].x, b[j].y);
                    mma16816(acc[i][j], ah, b[j].z, b[j].w);
                    mma16816(acc[i][j], al, b[j].x, b[j].y);
                }
            }
        }
        __syncthreads();
    }

    // ---- epilogue from register fragments ----
    // thread rows: row0 + mq*64 + i*16 + h*8 + lane/4 ; cols: nh*32 + j*8 + (lane&3)*2
    const int rb = row0 + mq*64 + (lane >> 2);
    const int cb = nh*32 + (lane & 3)*2;
    #pragma unroll
    for (int i = 0; i < 4; i++){
        #pragma unroll
        for (int h = 0; h < 2; h++){
            int row = rb + i*16 + h*8;
            if (row >= M) continue;
            float f[8];
            #pragma unroll
            for (int j = 0; j < 4; j++){
                f[2*j]   = acc[i][j][2*h];
                f[2*j+1] = acc[i][j][2*h+1];
                if (OUTACT){ f[2*j] = selu_f(f[2*j]); f[2*j+1] = selu_f(f[2*j+1]); }
            }
            if (DOTOUT){
                float s = 0.f;
                #pragma unroll
                for (int j = 0; j < 4; j++){
                    float2 wv = *(const float2*)(Wf3 + cb + j*8);
                    s += f[2*j]*wv.x + f[2*j+1]*wv.y;
                }
                s += __shfl_xor_sync(0xffffffffu, s, 1);
                s += __shfl_xor_sync(0xffffffffu, s, 2);
                if ((lane & 3) == 0) atomicAdd(qout + row, s);  // row split across nh warps
            } else {
                float* cp = C + (size_t)row*ML + cb;
                #pragma unroll
                for (int j = 0; j < 4; j++)
                    *(float2*)(cp + j*8) = make_float2(f[2*j], f[2*j+1]);
                if (AGGMAX){
                    unsigned* ap = aggU + (size_t)rcv[row]*ML + cb;
                    #pragma unroll
                    for (int j = 0; j < 4; j++){
                        atomicMax(ap + j*8,     fenc(f[2*j]));
                        atomicMax(ap + j*8 + 1, fenc(f[2*j+1]));
                    }
                }
            }
        }
    }
}

// ---------------- elementwise / segment kernels ----------------
__global__ void k_hstar(const float* __restrict__ x, float* __restrict__ h){
    int n = blockIdx.x*blockDim.x + threadIdx.x;
    if (n < NN) h[n] = x[2*n];
}
__global__ void k_copy(const float* __restrict__ a, float* __restrict__ b, int n){
    int i = blockIdx.x*blockDim.x + threadIdx.x;
    if (i < n) b[i] = a[i];
}
__global__ void k_zero(float* __restrict__ p, int n){
    int i = blockIdx.x*blockDim.x + threadIdx.x;
    if (i < n) p[i] = 0.f;
}
__global__ void k_fill_u(unsigned* __restrict__ p, unsigned v, int n){
    int i = blockIdx.x*blockDim.x + threadIdx.x;
    if (i < n) p[i] = v;
}
__global__ void k_flows(const float* __restrict__ h, const float* __restrict__ r,
                        const int* __restrict__ s, const int* __restrict__ rc,
                        float* __restrict__ q){
    int e = blockIdx.x*blockDim.x + threadIdx.x;
    if (e >= EE) return;
    float dh = h[s[e]] - h[rc[e]];
    q[e] = signf(dh) * __powf((fabsf(dh) + ZETA) / (r[e] + ZETA), INVP);
}
__global__ void k_segsum(const float* __restrict__ q, const int* __restrict__ rc,
                         float* __restrict__ d){
    int e = blockIdx.x*blockDim.x + threadIdx.x;
    if (e < EE) atomicAdd(&d[rc[e]], q[e]);
}
__global__ void k_node_in(const float* __restrict__ dh, const float* __restrict__ x,
                          const float* __restrict__ W, float* __restrict__ g){
    int idx = blockIdx.x*blockDim.x + threadIdx.x;
    if (idx >= NN*ML) return;
    int n = idx >> 7, j = idx & 127;
    g[idx] = selu_f(dh[n]) * W[j] + selu_f(x[2*n+1]) * W[ML + j];
}
__global__ void k_edge_in(const float* __restrict__ qt, const float* __restrict__ qh,
                          const float* __restrict__ W, float* __restrict__ z){
    long idx = (long)blockIdx.x*blockDim.x + threadIdx.x;
    if (idx >= (long)EE*ML) return;
    int e = (int)(idx >> 7), j = (int)(idx & 127);
    z[idx] = selu_f(qt[e]) * W[j] + selu_f(qh[e]) * W[ML + j];
}
__global__ void k_antisym(float* __restrict__ q){
    int idx = blockIdx.x*blockDim.x + threadIdx.x;
    if (idx >= BC*E2C) return;
    int b = idx / E2C, i = idx % E2C;
    q[b*EPGC + E2C + i] = -q[b*EPGC + i];
}
__global__ void k_hl(const float* __restrict__ q, const float* __restrict__ r,
                     float* __restrict__ hl){
    int e = blockIdx.x*blockDim.x + threadIdx.x;
    if (e >= EE) return;
    float qe = q[e];
    float aq = fabsf(qe);
    float p  = (aq < 1e-30f) ? 0.f : __powf(aq, PEXP);
    hl[e] = r[e] * signf(qe) * p;
}
__global__ void k_head_edge(const float* __restrict__ h, const float* __restrict__ hl,
                            const int* __restrict__ s, const int* __restrict__ rc,
                            unsigned* __restrict__ agg){
    int e = blockIdx.x*blockDim.x + threadIdx.x;
    if (e < EE) atomicMax(&agg[rc[e]], fenc(h[s[e]] - hl[e]));
}
// reads agg[n] and resets it to ENC_NEGINF (so no per-iteration fill pass is needed)
__global__ void k_head_node(unsigned* __restrict__ agg, const float* __restrict__ hold,
                            const float* __restrict__ x, float* __restrict__ hnew){
    int n = blockIdx.x*blockDim.x + threadIdx.x;
    if (n >= NN) return;
    float hs = x[2*n];
    unsigned u = agg[n];
    agg[n] = ENC_NEGINF;
    float a = (u == ENC_NEGINF) ? -INFINITY : fdec(u);
    hnew[n] = (hs != 0.f) ? hs : fmaxf(hold[n], a);
}

// ---------------- host orchestration ----------------
template<typename T>
static T* sym_addr(const void* sym){
    void* p = nullptr;
    cudaGetSymbolAddress(&p, sym);
    return (T*)p;
}
static void set_smem(const void* f){
    cudaFuncSetAttribute(f, cudaFuncAttributeMaxDynamicSharedMemorySize, SM_TOT);
}

extern "C" void kernel_launch(void* const* d_in, const int* in_sizes, int n_in,
                              void* d_out, int out_size)
{
    const float* x    = (const float*)d_in[0];
    const float* r    = (const float*)d_in[1];
    const float* Wni  = (const float*)d_in[2];
    const float* Wei  = (const float*)d_in[3];
    const float* Wf1  = (const float*)d_in[4];
    const float* Wf2  = (const float*)d_in[5];
    const float* Wf3  = (const float*)d_in[6];
    const float* We1  = (const float*)d_in[7];
    const float* We2  = (const float*)d_in[8];
    const float* Wn1  = (const float*)d_in[9];
    const float* Wn2  = (const float*)d_in[10];
    const int*   sndr = (const int*)d_in[11];
    const int*   rcvr = (const int*)d_in[12];
    float*       out  = (float*)d_out;

    float*    g   = sym_addr<float>(g_buf);
    unsigned* agu = sym_addr<unsigned>(agg_buf);
    float*    tN  = sym_addr<float>(tN_buf);
    float*    u   = sym_addr<float>(u_buf);
    float*    v   = sym_addr<float>(v_buf);
    float*    z   = sym_addr<float>(z_buf);
    float*    w   = sym_addr<float>(w_buf);
    float*    qh  = sym_addr<float>(qh_buf);
    float*    qt  = sym_addr<float>(qt_buf);
    float*    hl  = sym_addr<float>(hl_buf);
    float*    dh  = sym_addr<float>(dh_buf);
    float*    hA  = sym_addr<float>(hA_buf);
    float*    hB  = sym_addr<float>(hB_buf);
    unsigned* agS = sym_addr<unsigned>(aggS_buf);
    unsigned short* WP = sym_addr<unsigned short>(wpk_buf);

    set_smem((const void*)tcg<1,M_SELU ,false,false,false>);
    set_smem((const void*)tcg<1,M_SUM3 ,false,true ,false>);
    set_smem((const void*)tcg<2,M_CAT2D,true ,false,false>);
    set_smem((const void*)tcg<1,M_PLAIN,false,false,false>);
    set_smem((const void*)tcg<1,M_SUM3 ,true ,false,true >);

    const int T = 256;
    const int gN  = (NN + T - 1) / T;
    const int gE  = (EE + T - 1) / T;
    const int gNM = (NN*ML + T - 1) / T;
    const long EM = (long)EE*ML;
    const int gEM = (int)((EM + T - 1) / T);

    const int  TE = (EE + 127)/128;          // 1000 edge tiles
    const int  TN = (NN + 127)/128;          // 313 node tiles
    const dim3 GN2(TN, 2);

    #define CHK(i) (WP + (size_t)(i)*32768)

    // ---- weight prep ----
    // We1: 0..8 | We2: 9..11 | Wn1: 12..17 | Wn2: 18..20 | Wf1: 21..23 | Wf2: 24
    k_prep<<<9, 256>>>(We1, 3, 384*ML, 0);
    k_prep<<<3, 256>>>(We2, 1, ML*ML, 9);
    k_prep<<<6, 256>>>(Wn1, 2, 256*ML, 12);
    k_prep<<<3, 256>>>(Wn2, 1, ML*ML, 18);
    k_prep<<<3, 256>>>(Wf1, 3, 0, 21);
    k_prep<<<1, 256>>>(Wf2, 1, 0, 24);

    // ---- initial flows ----
    k_hstar<<<gN, T>>>(x, hA);
    k_flows<<<gE, T>>>(hA, r, sndr, rcvr, qh);
    k_zero<<<gN, T>>>(dh, NN);
    k_segsum<<<gE, T>>>(qh, rcvr, dh);
    k_copy<<<gE, T>>>(qh, qt, EE);
    k_fill_u<<<gN, T>>>(agS, ENC_NEGINF, NN);   // once; head-node resets each round

    for (int k = 0; k < K_ITERS; k++){
        k_node_in<<<gNM, T>>>(dh, x, Wni, g);
        k_edge_in<<<gEM, T>>>(qt, qh, Wei, z);

        for (int i = 0; i < I_LAYERS; i++){
            // u = selu(g)@We1[0:128], v = selu(g)@We1[128:256]
            tcg<1,M_SELU,false,false,false><<<GN2, 256, SM_TOT>>>(
                g, nullptr, nullptr, nullptr, nullptr, nullptr,
                CHK(i*3), u, v, nullptr, nullptr, nullptr, nullptr, NN);
            // w = selu(z)@We1[256:384]
            tcg<1,M_SELU,false,false,false><<<TE, 256, SM_TOT>>>(
                z, nullptr, nullptr, nullptr, nullptr, nullptr,
                CHK(i*3+2), w, nullptr, nullptr, nullptr, nullptr, nullptr, EE);
            // z = selu(u[s]+v[r]+w) @ We2  (+ fused segment-max)
            k_fill_u<<<gNM, T>>>(agu, ENC_NEGINF, NN*ML);
            tcg<1,M_SUM3,false,true,false><<<TE, 256, SM_TOT>>>(
                u, v, w, nullptr, sndr, rcvr,
                CHK(9+i), z, nullptr, agu, rcvr, nullptr, nullptr, EE);
            // tN = selu([selu(g), selu(dec(agu))] @ Wn1)
            tcg<2,M_CAT2D,true,false,false><<<TN, 256, SM_TOT>>>(
                g, nullptr, nullptr, agu, nullptr, nullptr,
                CHK(12+2*i), tN, nullptr, nullptr, nullptr, nullptr, nullptr, NN);
            // g = tN @ Wn2
            tcg<1,M_PLAIN,false,false,false><<<TN, 256, SM_TOT>>>(
                tN, nullptr, nullptr, nullptr, nullptr, nullptr,
                CHK(18+i), g, nullptr, nullptr, nullptr, nullptr, nullptr, NN);
        }

        // flow head
        tcg<1,M_SELU,false,false,false><<<GN2, 256, SM_TOT>>>(
            g, nullptr, nullptr, nullptr, nullptr, nullptr,
            CHK(21), u, v, nullptr, nullptr, nullptr, nullptr, NN);
        tcg<1,M_SELU,false,false,false><<<TE, 256, SM_TOT>>>(
            z, nullptr, nullptr, nullptr, nullptr, nullptr,
            CHK(23), w, nullptr, nullptr, nullptr, nullptr, nullptr, EE);
        tcg<1,M_SUM3,true,false,true><<<TE, 256, SM_TOT>>>(
            u, v, w, nullptr, sndr, rcvr,
            CHK(24), nullptr, nullptr, nullptr, nullptr, Wf3, qh, EE);
        k_antisym<<<(BC*E2C + T - 1)/T, T>>>(qh);

        // d_hat
        k_zero<<<gN, T>>>(dh, NN);
        k_segsum<<<gE, T>>>(qh, rcvr, dh);

        // construct_heads
        k_hstar<<<gN, T>>>(x, hA);
        k_hl<<<gE, T>>>(qh, r, hl);
        float* hc = hA; float* hn = hB;
        for (int j = 0; j < J_HEADS; j++){
            k_head_edge<<<gE, T>>>(hc, hl, sndr, rcvr, agS);
            k_head_node<<<gN, T>>>(agS, hc, x, hn);
            float* t2 = hc; hc = hn; hn = t2;
        }

        k_flows<<<gE, T>>>(hc, r, sndr, rcvr, qt);
    }

    k_copy<<<gN, T>>>(hA, out, NN);
    (void)in_sizes; (void)n_in; (void)out_size;
    #undef CHK
}